// round 16
// baseline (speedup 1.0000x reference)
#include <cuda_runtime.h>
#include <math.h>
#include <stdint.h>

// ---------------- problem constants ----------------
#define T       4096
#define HID     400
#define HIDP    416           // padded h buffer (zeros in pad)
#define G4      1600          // 4*HID
#define EMB     50
#define E3      150           // 3*EMB
#define KEY     300
#define K4      1200          // 4*KEY

// rtoken: T*E3 = 614400 floats; ktoken: 400; context: T*32*HID = 52428800
#define OFF_KTOK  614400
#define OFF_CTX   614800

#define CL      16            // cluster size (CTAs per recurrence group)
#define CELLS   25            // cells per CTA (16*25 = 400)
#define ROWS    100           // gate rows per CTA
#define THREADS 448           // 14 warps: 11x2 cells + 3x1 cell

// ---------------- scratch (static device globals; no allocation) ----------------
__device__ float    g_xg0[(size_t)T * G4];   // layer0 input gates (+both biases)
__device__ float    g_u[(size_t)T * G4];     // layer1 input gates u[t]=Wih1*h0[t]+biases
__device__ float    g_h0[(T + 1) * HID];     // h0 timeline (global copy for helpers)
__device__ float    g_h1[(T + 1) * HID];     // h1 timeline (for rtoken/ctx/key)
__device__ unsigned g_cnt0[(T + 1) * 32];    // h0 slot-ready counters (one 128B line each)
__device__ unsigned g_cntu[(T + 1) * 32];    // u[t]-ready counters
__device__ float    g_kgate[K4];             // key lstm pre-activation gates

// ---------------- helpers ----------------
__device__ __forceinline__ float sigf(float x) {
    return __fdividef(1.f, 1.f + __expf(-x));
}
__device__ __forceinline__ float tanhf_(float x) {
    x = fminf(15.f, fmaxf(-15.f, x));
    float e = __expf(-2.f * x);
    return __fdividef(1.f - e, 1.f + e);
}
__device__ __forceinline__ float wsum(float v) {
#pragma unroll
    for (int o = 16; o > 0; o >>= 1) v += __shfl_xor_sync(0xffffffffu, v, o);
    return v;
}
__device__ __forceinline__ unsigned ld_acq(const unsigned* p) {
    unsigned v;
    asm volatile("ld.acquire.gpu.global.u32 %0, [%1];" : "=r"(v) : "l"(p) : "memory");
    return v;
}
__device__ __forceinline__ void red_rel(unsigned* p) {
    asm volatile("red.release.gpu.global.add.u32 [%0], %1;" :: "l"(p), "r"(1u) : "memory");
}
__device__ __forceinline__ uint32_t smem_u32(const void* p) {
    uint32_t a;
    asm("{ .reg .u64 t; cvta.to.shared.u64 t, %1; cvt.u32.u64 %0, t; }" : "=r"(a) : "l"(p));
    return a;
}
__device__ __forceinline__ uint32_t mapa_u32(uint32_t laddr, uint32_t rank) {
    uint32_t r;
    asm("mapa.shared::cluster.u32 %0, %1, %2;" : "=r"(r) : "r"(laddr), "r"(rank));
    return r;
}

// multi-value butterfly: 8 sums in 9 shfls; lane L ends with sum(a[L&7])
__device__ __forceinline__ float reduce8(const float* a, int lane) {
    float v01 = (lane & 1) ? a[1] : a[0];
    v01 += __shfl_xor_sync(0xffffffffu, (lane & 1) ? a[0] : a[1], 1);
    float v23 = (lane & 1) ? a[3] : a[2];
    v23 += __shfl_xor_sync(0xffffffffu, (lane & 1) ? a[2] : a[3], 1);
    float v45 = (lane & 1) ? a[5] : a[4];
    v45 += __shfl_xor_sync(0xffffffffu, (lane & 1) ? a[4] : a[5], 1);
    float v67 = (lane & 1) ? a[7] : a[6];
    v67 += __shfl_xor_sync(0xffffffffu, (lane & 1) ? a[6] : a[7], 1);
    float v03 = (lane & 2) ? v23 : v01;
    v03 += __shfl_xor_sync(0xffffffffu, (lane & 2) ? v01 : v23, 2);
    float v47 = (lane & 2) ? v67 : v45;
    v47 += __shfl_xor_sync(0xffffffffu, (lane & 2) ? v45 : v67, 2);
    float v = (lane & 4) ? v47 : v03;
    v += __shfl_xor_sync(0xffffffffu, (lane & 4) ? v03 : v47, 4);
    v += __shfl_xor_sync(0xffffffffu, v, 8);
    v += __shfl_xor_sync(0xffffffffu, v, 16);
    return v;
}
// 4 sums in 6 shfls; lane L ends with sum(a[L&3])
__device__ __forceinline__ float reduce4(const float* a, int lane) {
    float v01 = (lane & 1) ? a[1] : a[0];
    v01 += __shfl_xor_sync(0xffffffffu, (lane & 1) ? a[0] : a[1], 1);
    float v23 = (lane & 1) ? a[3] : a[2];
    v23 += __shfl_xor_sync(0xffffffffu, (lane & 1) ? a[2] : a[3], 1);
    float v = (lane & 2) ? v23 : v01;
    v += __shfl_xor_sync(0xffffffffu, (lane & 2) ? v01 : v23, 2);
    v += __shfl_xor_sync(0xffffffffu, v, 4);
    v += __shfl_xor_sync(0xffffffffu, v, 8);
    v += __shfl_xor_sync(0xffffffffu, v, 16);
    return v;
}

// cluster-scope mbarrier ops
__device__ __forceinline__ void mbar_init(uint32_t addr, unsigned count) {
    asm volatile("mbarrier.init.shared.b64 [%0], %1;" :: "r"(addr), "r"(count) : "memory");
}
__device__ __forceinline__ void mbar_arrive_remote(uint32_t laddr, uint32_t peer) {
    uint32_t ra = mapa_u32(laddr, peer);
    asm volatile("mbarrier.arrive.release.cluster.shared::cluster.b64 _, [%0];"
                 :: "r"(ra) : "memory");
}
__device__ __forceinline__ void mbar_wait_cluster(uint32_t addr, uint32_t parity) {
    uint32_t done;
    asm volatile(
        "{\n\t.reg .pred p;\n\t"
        "mbarrier.try_wait.parity.acquire.cluster.shared::cta.b64 p, [%1], %2;\n\t"
        "selp.b32 %0, 1, 0, p;\n\t}"
        : "=r"(done) : "r"(addr), "r"(parity) : "memory");
    while (!done) {
        asm volatile(
            "{\n\t.reg .pred p;\n\t"
            "mbarrier.try_wait.parity.acquire.cluster.shared::cta.b64 p, [%1], %2, 0x989680;\n\t"
            "selp.b32 %0, 1, 0, p;\n\t}"
            : "=r"(done) : "r"(addr), "r"(parity) : "memory");
    }
}
__device__ __forceinline__ void st_cluster_b32(uint32_t ra, float v) {
    asm volatile("st.shared::cluster.b32 [%0], %1;" :: "r"(ra), "r"(__float_as_uint(v)) : "memory");
}

// ---------------- init: counters ----------------
__global__ void init_kernel() {
    int i = blockIdx.x * blockDim.x + threadIdx.x;
    if (i < (T + 1) * 32) {
        g_cnt0[i] = 0u;
        g_cntu[i] = 0u;
    }
    if (i < HID) { g_h0[i] = 0.f; g_h1[i] = 0.f; }
}

// no-op spacer so the ncu capture slot lands on lstm_main_kernel
__global__ void noop_kernel() {}

// ---------------- kernel A: xg0 = concat-embed @ Wih0^T + bih0 + bhh0 ----------------
__global__ void __launch_bounds__(256, 1) xg0_kernel(
    const int* __restrict__ xr, const int* __restrict__ xcpc, const int* __restrict__ xma,
    const float* __restrict__ em, const float* __restrict__ ec, const float* __restrict__ er,
    const float* __restrict__ Wih0, const float* __restrict__ bih0, const float* __restrict__ bhh0)
{
    __shared__ float xs[64][53];
    __shared__ float ws[160][53];
    const int bt0 = blockIdx.x * 64;
    const int br0 = blockIdx.y * 160;
    const int tid = threadIdx.x;
    float acc[8][5];
#pragma unroll
    for (int i = 0; i < 8; i++)
#pragma unroll
        for (int r = 0; r < 5; r++) acc[i][r] = 0.f;

    for (int ch = 0; ch < 3; ch++) {
        const float* tab = (ch == 0) ? em : ((ch == 1) ? ec : er);
        const int* idx = (ch == 0) ? xma : ((ch == 1) ? xcpc : xr);
        for (int i = tid; i < 64 * 50; i += 256) {
            int tt = i / 50, kk = i - tt * 50;
            xs[tt][kk] = tab[idx[bt0 + tt] * EMB + kk];
        }
        for (int i = tid; i < 160 * 50; i += 256) {
            int rr = i / 50, kk = i - rr * 50;
            ws[rr][kk] = Wih0[(br0 + rr) * E3 + ch * 50 + kk];
        }
        __syncthreads();
        const int tr = tid & 31, tc = tid >> 5;
#pragma unroll 5
        for (int kk = 0; kk < 50; kk++) {
            float a[8], wv[5];
#pragma unroll
            for (int i = 0; i < 8; i++) a[i] = xs[tc * 8 + i][kk];
#pragma unroll
            for (int r = 0; r < 5; r++) wv[r] = ws[tr * 5 + r][kk];
#pragma unroll
            for (int i = 0; i < 8; i++)
#pragma unroll
                for (int r = 0; r < 5; r++) acc[i][r] = fmaf(a[i], wv[r], acc[i][r]);
        }
        __syncthreads();
    }
    const int tr = tid & 31, tc = tid >> 5;
#pragma unroll
    for (int r = 0; r < 5; r++) {
        int rg = br0 + tr * 5 + r;
        float bias = bih0[rg] + bhh0[rg];
#pragma unroll
        for (int i = 0; i < 8; i++) {
            int t = bt0 + tc * 8 + i;
            g_xg0[(size_t)t * G4 + rg] = acc[i][r] + bias;
        }
    }
}

// ---------------- kernel B: persistent recurrence with DSMEM clusters ----------------
// R16 vs R13 (single structural change): warp-owns-cells COMPUTE (MUFU cell phase
// moves into the parallel section; cst lives in lanes 0..nc-1 of each warp), while
// keeping R13's single-warp fan-out + 16 arrives/step (per-thread release = safe).
// 14 warps: warps 0-10 own cells {2w,2w+1} (8 rows); warps 11-13 own cell 11+w (4 rows).
__global__ void __launch_bounds__(THREADS, 1) lstm_main_kernel(
    const float* __restrict__ Whh0,
    const float* __restrict__ Wih1,
    const float* __restrict__ Whh1,
    const float* __restrict__ bih1,
    const float* __restrict__ bhh1)
{
    const int tid  = threadIdx.x;
    const int warp = tid >> 5;
    const int lane = tid & 31;
    const int role = blockIdx.x >> 4;    // 0=L0, 1=L1, 2=helpers
    const int rank = blockIdx.x & 15;

    if (role == 2) {
        // ---------------- helpers: u[t] = Wih1 * h0[t] + (bih1+bhh1) ----------------
        // 14 warps x 8 rows (f = warp*8 + r, guarded to ROWS); pure reduce8.
        __shared__ __align__(16) float hb2[2][HIDP];   // staged h0 (double buffer)
        float w[8][13];
#pragma unroll
        for (int r = 0; r < 8; r++) {
            int f = warp * 8 + r;
            bool fv = (f < ROWS);
            int row = fv ? ((f & 3) * 400 + rank * CELLS + (f >> 2)) : 0;
#pragma unroll
            for (int c = 0; c < 13; c++) {
                int k = lane + 32 * c;
                w[r][c] = (fv && k < HID) ? Wih1[(size_t)row * HID + k] : 0.f;
            }
        }
        float bias = 0.f;
        int doff = 0;
        bool stv = false;
        if (lane < 8) {
            int f = warp * 8 + lane;
            if (f < ROWS) {
                int cell = rank * CELLS + (f >> 2);
                bias = bih1[(f & 3) * 400 + cell] + bhh1[(f & 3) * 400 + cell];
                doff = (f & 3) * 400 + cell;
                stv = true;
            }
        }
        for (int i = tid; i < 2 * HIDP; i += THREADS) ((float*)hb2)[i] = 0.f;
        __syncthreads();
        // bootstrap: stage h0[0] (slot 1) into hb2[0]
        if (warp == 1) {
            const unsigned* cp = g_cnt0 + 32;          // cnt0[1]
            while (ld_acq(cp) < CL) {}
            for (int i = lane; i < HID; i += 32)
                hb2[0][i] = __ldcg(g_h0 + (size_t)HID + i);
        }
        __syncthreads();

        for (int t = 0; t < T; t++) {
            // warps 1,2: poll + issue h0[t+1] loads EARLY (load-use distance = FMA phase)
            float pre[7];
            const bool pf = (warp == 1 || warp == 2) && (t < T - 1);
            if (pf) {
                const unsigned* cp = g_cnt0 + (size_t)(t + 2) * 32;
                while (ld_acq(cp) < CL) {}
                const float* hn = g_h0 + (size_t)(t + 2) * HID;
#pragma unroll
                for (int c = 0; c < 7; c++) {
                    int k = lane + 32 * ((warp - 1) + 2 * c);
                    pre[c] = (k < HID) ? __ldcg(hn + k) : 0.f;
                }
            }
            const float* hb = &hb2[t & 1][0];
            float hv[13];
#pragma unroll
            for (int c = 0; c < 13; c++) hv[c] = hb[lane + 32 * c];   // pads zero
            float a[8];
#pragma unroll
            for (int r = 0; r < 8; r++) a[r] = 0.f;
#pragma unroll
            for (int c = 0; c < 13; c++)
#pragma unroll
                for (int r = 0; r < 8; r++) a[r] = fmaf(w[r][c], hv[c], a[r]);
            float v = reduce8(a, lane);           // lanes 0-7 -> row sums
            if (stv) __stcg(g_u + (size_t)t * G4 + doff, v + bias);
            if (pf) {
                float* dst = &hb2[(t + 1) & 1][0];
#pragma unroll
                for (int c = 0; c < 7; c++) {
                    int k = lane + 32 * ((warp - 1) + 2 * c);
                    if (k < HID) dst[k] = pre[c];
                }
            }
            __syncthreads();
            if (tid == 0) red_rel(g_cntu + (size_t)t * 32);
        }
        return;
    }

    // ---------------- recurrence clusters (L0 / L1), warp-owns-cells compute ----------------
    __shared__ __align__(16) float hbuf[2][HIDP];
    __shared__ __align__(16) float hstage[28];
    __shared__ __align__(16) float4 ubuf4[2][CELLS];   // staged u (L1 only)
    __shared__ __align__(8)  unsigned long long mbar;

    const float* Whh = (role == 0) ? Whh0 : Whh1;
    float* ghout     = (role == 0) ? g_h0 : g_h1;

    const int nc    = (warp < 11) ? 2 : 1;             // cells owned by this warp
    const int cbase = (warp < 11) ? 2 * warp : (11 + warp);  // 22,23,24 for warps 11-13

    float w[8][13];                                    // row j: cell cbase+(j>>2), gate j&3
#pragma unroll
    for (int r = 0; r < 8; r++) {
        bool rv = (r < 4 * nc);
        int row = rv ? ((r & 3) * 400 + rank * CELLS + cbase + (r >> 2)) : 0;
#pragma unroll
        for (int c = 0; c < 13; c++) {
            int k = lane + 32 * c;
            w[r][c] = (rv && k < HID) ? Whh[(size_t)row * HID + k] : 0.f;
        }
    }
    const uint32_t hbuf_a = smem_u32(&hbuf[0][0]);
    const uint32_t mbar_a = smem_u32(&mbar);

    for (int i = tid; i < 2 * HIDP; i += THREADS) ((float*)hbuf)[i] = 0.f;
    if (tid == 0) mbar_init(mbar_a, CL);
    __syncthreads();
    // bootstrap: L1 stages u[0] (helpers produce it without L1 involvement — no cycle)
    if (role == 1 && warp == 1) {
        const unsigned* cu = g_cntu;                   // cntu[0]
        while (ld_acq(cu) < CL) {}
        if (lane < CELLS) {
            const float* up = g_u + rank * CELLS + lane;
            ubuf4[0][lane] = make_float4(__ldcg(up), __ldcg(up + 400),
                                         __ldcg(up + 800), __ldcg(up + 1200));
        }
    }
    asm volatile("barrier.cluster.arrive.aligned;" ::: "memory");
    asm volatile("barrier.cluster.wait.aligned;" ::: "memory");

    float cst = 0.f;                                   // lives in lanes 0..nc-1
    for (int t = 0; t < T; t++) {
        float x0 = 0.f, x1 = 0.f, x2 = 0.f, x3 = 0.f;
        float4 upre = make_float4(0.f, 0.f, 0.f, 0.f);
        if (role == 0 && lane < nc) {
            // xg0 precomputed: prefetch own cells' gates before wait (off critical path)
            const float* xg = g_xg0 + (size_t)t * G4 + rank * CELLS + cbase + lane;
            x0 = __ldg(xg); x1 = __ldg(xg + 400); x2 = __ldg(xg + 800); x3 = __ldg(xg + 1200);
        }
        if (role == 1 && warp == 1 && t < T - 1) {
            // prefetch u[t+1]: helpers run ahead -> poll hits; LDG latency hides under FMA
            const unsigned* cu = g_cntu + (size_t)(t + 1) * 32;
            while (ld_acq(cu) < CL) {}
            if (lane < CELLS) {
                const float* up = g_u + (size_t)(t + 1) * G4 + rank * CELLS + lane;
                upre = make_float4(__ldcg(up), __ldcg(up + 400),
                                   __ldcg(up + 800), __ldcg(up + 1200));
            }
        }
        // wait for h[t] (phase t-1); step 0 reads the zero-initialized buffer
        if (t > 0) mbar_wait_cluster(mbar_a, (unsigned)((t - 1) & 1));

        const float* hb = &hbuf[t & 1][0];
        float hv[13];
#pragma unroll
        for (int c = 0; c < 13; c++) hv[c] = hb[lane + 32 * c];   // pads are zero
        float v;
        if (nc == 2) {
            float a[8];
#pragma unroll
            for (int r = 0; r < 8; r++) a[r] = 0.f;
#pragma unroll
            for (int c = 0; c < 13; c++)
#pragma unroll
                for (int r = 0; r < 8; r++) a[r] = fmaf(w[r][c], hv[c], a[r]);
            v = reduce8(a, lane);                      // lane L: sum(a[L&7])
        } else {
            float a[4];
#pragma unroll
            for (int r = 0; r < 4; r++) a[r] = 0.f;
#pragma unroll
            for (int c = 0; c < 13; c++)
#pragma unroll
                for (int r = 0; r < 4; r++) a[r] = fmaf(w[r][c], hv[c], a[r]);
            v = reduce4(a, lane);                      // lane L: sum(a[L&3])
        }
        // gather own cell's gates: lane0 <- idx 0..3, lane1 <- idx 4..7 (nc==2)
        float g0 = __shfl_sync(0xffffffffu, v, (4 * lane) & 31);
        float g1 = __shfl_sync(0xffffffffu, v, (4 * lane + 1) & 31);
        float g2 = __shfl_sync(0xffffffffu, v, (4 * lane + 2) & 31);
        float g3 = __shfl_sync(0xffffffffu, v, (4 * lane + 3) & 31);
        if (lane < nc) {
            if (role == 1) {
                float4 uv = ubuf4[t & 1][cbase + lane];   // staged u[t]
                x0 = uv.x; x1 = uv.y; x2 = uv.z; x3 = uv.w;
            }
            float gi = sigf(g0 + x0);
            float gf = sigf(g1 + x1);
            float gg = tanhf_(g2 + x2);
            float go = sigf(g3 + x3);
            cst = gf * cst + gi * gg;
            float h = go * tanhf_(cst);
            hstage[cbase + lane] = h;
            __stcg(ghout + (size_t)(t + 1) * HID + rank * CELLS + cbase + lane, h);
        }
        if (role == 1 && warp == 1 && t < T - 1 && lane < CELLS)
            ubuf4[(t + 1) & 1][lane] = upre;
        __syncthreads();

        if (warp == 0) {
            if (lane < CL) {
                // copy this CTA's 25-float slice into peer `lane`'s next h buffer
                float s[CELLS];
#pragma unroll
                for (int q = 0; q < CELLS; q++) s[q] = hstage[q];
                uint32_t dst = mapa_u32(
                    hbuf_a + (uint32_t)(((t + 1) & 1) * HIDP + rank * CELLS) * 4u,
                    (uint32_t)lane);
#pragma unroll
                for (int q = 0; q < CELLS; q++) st_cluster_b32(dst + 4u * q, s[q]);
                mbar_arrive_remote(mbar_a, (uint32_t)lane);
            }
            __syncwarp();
            if (role == 0 && lane == 0) red_rel(g_cnt0 + (size_t)(t + 1) * 32);
        }
    }
    // final cluster barrier: no CTA exits while peers may still write its smem
    asm volatile("barrier.cluster.arrive.aligned;" ::: "memory");
    asm volatile("barrier.cluster.wait.aligned;" ::: "memory");
}

// ---------------- kernel C: rtoken = rnn_out @ fcW^T + fcb ----------------
__global__ void __launch_bounds__(256, 1) rtoken_kernel(
    const float* __restrict__ fcW, const float* __restrict__ fcb, float* __restrict__ out)
{
    __shared__ float xs[64][53];
    __shared__ float ws[160][53];
    const int bt0 = blockIdx.x * 64;
    const int tid = threadIdx.x;
    float acc[8][5];
#pragma unroll
    for (int i = 0; i < 8; i++)
#pragma unroll
        for (int r = 0; r < 5; r++) acc[i][r] = 0.f;

    for (int ch = 0; ch < 8; ch++) {
        int k0 = ch * 50;
        for (int i = tid; i < 64 * 50; i += 256) {
            int tt = i / 50, kk = i - tt * 50;
            xs[tt][kk] = g_h1[(size_t)(bt0 + tt + 1) * HID + k0 + kk];
        }
        for (int i = tid; i < 160 * 50; i += 256) {
            int rr = i / 50, kk = i - rr * 50;
            ws[rr][kk] = (rr < E3) ? fcW[rr * HID + k0 + kk] : 0.f;
        }
        __syncthreads();
        const int tr = tid & 31, tc = tid >> 5;
#pragma unroll 5
        for (int kk = 0; kk < 50; kk++) {
            float a[8], wv[5];
#pragma unroll
            for (int i = 0; i < 8; i++) a[i] = xs[tc * 8 + i][kk];
#pragma unroll
            for (int r = 0; r < 5; r++) wv[r] = ws[tr * 5 + r][kk];
#pragma unroll
            for (int i = 0; i < 8; i++)
#pragma unroll
                for (int r = 0; r < 5; r++) acc[i][r] = fmaf(a[i], wv[r], acc[i][r]);
        }
        __syncthreads();
    }
    const int tr = tid & 31, tc = tid >> 5;
#pragma unroll
    for (int r = 0; r < 5; r++) {
        int rg = tr * 5 + r;
        if (rg < E3) {
            float bias = fcb[rg];
#pragma unroll
            for (int i = 0; i < 8; i++) {
                int t = bt0 + tc * 8 + i;
                out[(size_t)t * E3 + rg] = acc[i][r] + bias;
            }
        }
    }
}

// ---------------- kernel D: context fill ----------------
__global__ void __launch_bounds__(128, 1) ctx_kernel(
    const float* __restrict__ actW, const float* __restrict__ actb,
    const float* __restrict__ Dp, float* __restrict__ out)
{
    const int t = blockIdx.x;
    const int warp = threadIdx.x >> 5, lane = threadIdx.x & 31;
    __shared__ float red[4];
    const float* hr = g_h1 + (size_t)(t + 1) * HID;
    const float* wrow = (warp < 3) ? (actW + warp * HID) : Dp;
    float acc = 0.f;
#pragma unroll
    for (int c = 0; c < 13; c++) {
        int k = lane + 32 * c;
        if (k < HID) acc = fmaf(__ldg(wrow + k), __ldg(hr + k), acc);
    }
    acc = wsum(acc);
    if (lane == 0) red[warp] = acc + ((warp < 3) ? actb[warp] : 0.f);
    __syncthreads();
    float l0 = red[0], l1 = red[1], l2 = red[2], d = red[3];
    float m = fmaxf(l0, fmaxf(l1, l2));
    float e0 = __expf(l0 - m), e1 = __expf(l1 - m), e2 = __expf(l2 - m);
    float p0 = __fdividef(e0, e0 + e1 + e2);
    float v = p0 * sigf(d);

    float4* dst = (float4*)(out + OFF_CTX + (size_t)t * 32 * HID);
    float4 vz = make_float4(v, v, v, v);
    float4 z = make_float4(0.f, 0.f, 0.f, 0.f);
    for (int q = threadIdx.x; q < 3200; q += 128) {
        __stcs(dst + q, (q < 100) ? vz : z);
    }
}

// ---------------- kernel E1: key lstm gates ----------------
__global__ void __launch_bounds__(128, 1) keygate_kernel(
    const float* __restrict__ kWih, const float* __restrict__ kbih, const float* __restrict__ kbhh)
{
    const int gw = blockIdx.x * 4 + (threadIdx.x >> 5);
    const int lane = threadIdx.x & 31;
    const float* hr = g_h1 + (size_t)T * HID;
    float hv[13];
#pragma unroll
    for (int c = 0; c < 13; c++) {
        int k = lane + 32 * c;
        hv[c] = (k < HID) ? __ldg(hr + k) : 0.f;
    }
    for (int rr = 0; rr < 30; rr++) {
        int r = gw * 30 + rr;
        float acc = 0.f;
#pragma unroll
        for (int c = 0; c < 13; c++) {
            int k = lane + 32 * c;
            if (k < HID) acc = fmaf(__ldg(kWih + (size_t)r * HID + k), hv[c], acc);
        }
        acc = wsum(acc);
        if (lane == 0) g_kgate[r] = acc + kbih[r] + kbhh[r];
    }
}

// ---------------- kernel E2: kh nonlinearity + ktoken ----------------
__global__ void __launch_bounds__(512, 1) keyout_kernel(
    const float* __restrict__ kfcW, const float* __restrict__ kfcb, float* __restrict__ out)
{
    __shared__ float kh[KEY];
    const int tid = threadIdx.x;
    if (tid < KEY) {
        float gi = g_kgate[tid], gg = g_kgate[600 + tid], go = g_kgate[900 + tid];
        float c = sigf(gi) * tanhf_(gg);
        kh[tid] = sigf(go) * tanhf_(c);
    }
    __syncthreads();
    const int warp = tid >> 5, lane = tid & 31;
    for (int rr = 0; rr < 25; rr++) {
        int r = warp * 25 + rr;
        float acc = 0.f;
#pragma unroll
        for (int c = 0; c < 10; c++) {
            int k = lane + 32 * c;
            if (k < KEY) acc = fmaf(__ldg(kfcW + (size_t)r * KEY + k), kh[k], acc);
        }
        acc = wsum(acc);
        if (lane == 0) out[OFF_KTOK + r] = acc + kfcb[r];
    }
}

// ---------------- launch ----------------
extern "C" void kernel_launch(void* const* d_in, const int* in_sizes, int n_in,
                              void* d_out, int out_size)
{
    const int*   xr       = (const int*)d_in[0];
    const int*   xcpc     = (const int*)d_in[1];
    const int*   xma      = (const int*)d_in[2];
    const float* em       = (const float*)d_in[3];
    const float* ec       = (const float*)d_in[4];
    const float* er       = (const float*)d_in[5];
    const float* Wih0     = (const float*)d_in[6];
    const float* Whh0     = (const float*)d_in[7];
    const float* bih0     = (const float*)d_in[8];
    const float* bhh0     = (const float*)d_in[9];
    const float* Wih1     = (const float*)d_in[10];
    const float* Whh1     = (const float*)d_in[11];
    const float* bih1     = (const float*)d_in[12];
    const float* bhh1     = (const float*)d_in[13];
    const float* fcW      = (const float*)d_in[14];
    const float* fcb      = (const float*)d_in[15];
    const float* actW     = (const float*)d_in[16];
    const float* actb     = (const float*)d_in[17];
    const float* Dp       = (const float*)d_in[18];
    const float* kWih     = (const float*)d_in[19];
    const float* kbih     = (const float*)d_in[21];
    const float* kbhh     = (const float*)d_in[22];
    const float* kfcW     = (const float*)d_in[23];
    const float* kfcb     = (const float*)d_in[24];
    float* out = (float*)d_out;

    init_kernel<<<((T + 1) * 32 + 255) / 256, 256>>>();
    xg0_kernel<<<dim3(T / 64, G4 / 160), 256>>>(xr, xcpc, xma, em, ec, er, Wih0, bih0, bhh0);
    noop_kernel<<<1, 32>>>();   // spacer: keeps lstm in the ncu capture slot

    // 16-CTA clusters (non-portable size): 3 clusters = L0 / L1 / helpers
    cudaFuncSetAttribute(lstm_main_kernel,
                         cudaFuncAttributeNonPortableClusterSizeAllowed, 1);
    cudaLaunchConfig_t cfg = {};
    cfg.gridDim = {48, 1, 1};
    cfg.blockDim = {THREADS, 1, 1};
    cfg.dynamicSmemBytes = 0;
    cfg.stream = 0;
    cudaLaunchAttribute attrs[1];
    attrs[0].id = cudaLaunchAttributeClusterDimension;
    attrs[0].val.clusterDim = {CL, 1, 1};
    cfg.attrs = attrs;
    cfg.numAttrs = 1;
    cudaLaunchKernelEx(&cfg, lstm_main_kernel, Whh0, Wih1, Whh1, bih1, bhh1);

    rtoken_kernel<<<T / 64, 256>>>(fcW, fcb, out);
    ctx_kernel<<<T, 128>>>(actW, actb, Dp, out);
    keygate_kernel<<<10, 128>>>(kWih, kbih, kbhh);
    keyout_kernel<<<1, 512>>>(kfcW, kfcb, out);
}

// round 17
// speedup vs baseline: 1.1148x; 1.1148x over previous
#include <cuda_runtime.h>
#include <math.h>
#include <stdint.h>

// ---------------- problem constants ----------------
#define T       4096
#define HID     400
#define HIDP    416           // padded h buffer (zeros in pad)
#define G4      1600          // 4*HID
#define EMB     50
#define E3      150           // 3*EMB
#define KEY     300
#define K4      1200          // 4*KEY

// rtoken: T*E3 = 614400 floats; ktoken: 400; context: T*32*HID = 52428800
#define OFF_KTOK  614400
#define OFF_CTX   614800

#define CL      16            // cluster size (CTAs per recurrence group)
#define CELLS   25            // cells per CTA (16*25 = 400)
#define ROWS    100           // gate rows per CTA
#define RPW     9             // row slots per warp (12 warps x 9 = 108, guarded to 100)
#define THREADS 384           // 12 warps

// ---------------- scratch (static device globals; no allocation) ----------------
__device__ float    g_xg0[(size_t)T * G4];   // layer0 input gates (+both biases)
__device__ float    g_u[(size_t)T * G4];     // layer1 input gates u[t]=Wih1*h0[t]+biases
__device__ float    g_h0[(T + 1) * HID];     // h0 timeline (global copy for helpers)
__device__ float    g_h1[(T + 1) * HID];     // h1 timeline (for rtoken/ctx/key)
__device__ unsigned g_cnt0[(T + 1) * 32];    // h0 slot-ready counters (one 128B line each)
__device__ unsigned g_cntu[(T + 1) * 32];    // u[t]-ready counters
__device__ float    g_kgate[K4];             // key lstm pre-activation gates

// ---------------- helpers ----------------
__device__ __forceinline__ float sigf(float x) {
    return __fdividef(1.f, 1.f + __expf(-x));
}
__device__ __forceinline__ float tanhf_(float x) {
    x = fminf(15.f, fmaxf(-15.f, x));
    float e = __expf(-2.f * x);
    return __fdividef(1.f - e, 1.f + e);
}
__device__ __forceinline__ float wsum(float v) {
#pragma unroll
    for (int o = 16; o > 0; o >>= 1) v += __shfl_xor_sync(0xffffffffu, v, o);
    return v;
}
__device__ __forceinline__ unsigned ld_acq(const unsigned* p) {
    unsigned v;
    asm volatile("ld.acquire.gpu.global.u32 %0, [%1];" : "=r"(v) : "l"(p) : "memory");
    return v;
}
__device__ __forceinline__ void red_rel(unsigned* p) {
    asm volatile("red.release.gpu.global.add.u32 [%0], %1;" :: "l"(p), "r"(1u) : "memory");
}
__device__ __forceinline__ uint32_t smem_u32(const void* p) {
    uint32_t a;
    asm("{ .reg .u64 t; cvta.to.shared.u64 t, %1; cvt.u32.u64 %0, t; }" : "=r"(a) : "l"(p));
    return a;
}
__device__ __forceinline__ uint32_t mapa_u32(uint32_t laddr, uint32_t rank) {
    uint32_t r;
    asm("mapa.shared::cluster.u32 %0, %1, %2;" : "=r"(r) : "r"(laddr), "r"(rank));
    return r;
}

// multi-value butterfly: 8 sums in 9 shfls; lane L ends with sum(a[L&7])
__device__ __forceinline__ float reduce8(const float* a, int lane) {
    float v01 = (lane & 1) ? a[1] : a[0];
    v01 += __shfl_xor_sync(0xffffffffu, (lane & 1) ? a[0] : a[1], 1);
    float v23 = (lane & 1) ? a[3] : a[2];
    v23 += __shfl_xor_sync(0xffffffffu, (lane & 1) ? a[2] : a[3], 1);
    float v45 = (lane & 1) ? a[5] : a[4];
    v45 += __shfl_xor_sync(0xffffffffu, (lane & 1) ? a[4] : a[5], 1);
    float v67 = (lane & 1) ? a[7] : a[6];
    v67 += __shfl_xor_sync(0xffffffffu, (lane & 1) ? a[6] : a[7], 1);
    float v03 = (lane & 2) ? v23 : v01;
    v03 += __shfl_xor_sync(0xffffffffu, (lane & 2) ? v01 : v23, 2);
    float v47 = (lane & 2) ? v67 : v45;
    v47 += __shfl_xor_sync(0xffffffffu, (lane & 2) ? v45 : v67, 2);
    float v = (lane & 4) ? v47 : v03;
    v += __shfl_xor_sync(0xffffffffu, (lane & 4) ? v03 : v47, 4);
    v += __shfl_xor_sync(0xffffffffu, v, 8);
    v += __shfl_xor_sync(0xffffffffu, v, 16);
    return v;
}

// cluster-scope mbarrier ops
__device__ __forceinline__ void mbar_init(uint32_t addr, unsigned count) {
    asm volatile("mbarrier.init.shared.b64 [%0], %1;" :: "r"(addr), "r"(count) : "memory");
}
__device__ __forceinline__ void mbar_arrive_remote(uint32_t laddr, uint32_t peer) {
    uint32_t ra = mapa_u32(laddr, peer);
    asm volatile("mbarrier.arrive.release.cluster.shared::cluster.b64 _, [%0];"
                 :: "r"(ra) : "memory");
}
__device__ __forceinline__ void mbar_wait_cluster(uint32_t addr, uint32_t parity) {
    uint32_t done;
    asm volatile(
        "{\n\t.reg .pred p;\n\t"
        "mbarrier.try_wait.parity.acquire.cluster.shared::cta.b64 p, [%1], %2;\n\t"
        "selp.b32 %0, 1, 0, p;\n\t}"
        : "=r"(done) : "r"(addr), "r"(parity) : "memory");
    while (!done) {
        asm volatile(
            "{\n\t.reg .pred p;\n\t"
            "mbarrier.try_wait.parity.acquire.cluster.shared::cta.b64 p, [%1], %2, 0x989680;\n\t"
            "selp.b32 %0, 1, 0, p;\n\t}"
            : "=r"(done) : "r"(addr), "r"(parity) : "memory");
    }
}
__device__ __forceinline__ void st_cluster_b32(uint32_t ra, float v) {
    asm volatile("st.shared::cluster.b32 [%0], %1;" :: "r"(ra), "r"(__float_as_uint(v)) : "memory");
}

// ---------------- init: counters ----------------
__global__ void init_kernel() {
    int i = blockIdx.x * blockDim.x + threadIdx.x;
    if (i < (T + 1) * 32) {
        g_cnt0[i] = 0u;
        g_cntu[i] = 0u;
    }
    if (i < HID) { g_h0[i] = 0.f; g_h1[i] = 0.f; }
}

// no-op spacer so the ncu capture slot lands on lstm_main_kernel
__global__ void noop_kernel() {}

// ---------------- kernel A: xg0 = concat-embed @ Wih0^T + bih0 + bhh0 ----------------
__global__ void __launch_bounds__(256, 1) xg0_kernel(
    const int* __restrict__ xr, const int* __restrict__ xcpc, const int* __restrict__ xma,
    const float* __restrict__ em, const float* __restrict__ ec, const float* __restrict__ er,
    const float* __restrict__ Wih0, const float* __restrict__ bih0, const float* __restrict__ bhh0)
{
    __shared__ float xs[64][53];
    __shared__ float ws[160][53];
    const int bt0 = blockIdx.x * 64;
    const int br0 = blockIdx.y * 160;
    const int tid = threadIdx.x;
    float acc[8][5];
#pragma unroll
    for (int i = 0; i < 8; i++)
#pragma unroll
        for (int r = 0; r < 5; r++) acc[i][r] = 0.f;

    for (int ch = 0; ch < 3; ch++) {
        const float* tab = (ch == 0) ? em : ((ch == 1) ? ec : er);
        const int* idx = (ch == 0) ? xma : ((ch == 1) ? xcpc : xr);
        for (int i = tid; i < 64 * 50; i += 256) {
            int tt = i / 50, kk = i - tt * 50;
            xs[tt][kk] = tab[idx[bt0 + tt] * EMB + kk];
        }
        for (int i = tid; i < 160 * 50; i += 256) {
            int rr = i / 50, kk = i - rr * 50;
            ws[rr][kk] = Wih0[(br0 + rr) * E3 + ch * 50 + kk];
        }
        __syncthreads();
        const int tr = tid & 31, tc = tid >> 5;
#pragma unroll 5
        for (int kk = 0; kk < 50; kk++) {
            float a[8], wv[5];
#pragma unroll
            for (int i = 0; i < 8; i++) a[i] = xs[tc * 8 + i][kk];
#pragma unroll
            for (int r = 0; r < 5; r++) wv[r] = ws[tr * 5 + r][kk];
#pragma unroll
            for (int i = 0; i < 8; i++)
#pragma unroll
                for (int r = 0; r < 5; r++) acc[i][r] = fmaf(a[i], wv[r], acc[i][r]);
        }
        __syncthreads();
    }
    const int tr = tid & 31, tc = tid >> 5;
#pragma unroll
    for (int r = 0; r < 5; r++) {
        int rg = br0 + tr * 5 + r;
        float bias = bih0[rg] + bhh0[rg];
#pragma unroll
        for (int i = 0; i < 8; i++) {
            int t = bt0 + tc * 8 + i;
            g_xg0[(size_t)t * G4 + rg] = acc[i][r] + bias;
        }
    }
}

// ---------------- kernel B: persistent recurrence with DSMEM clusters ----------------
// EXACT R13 (best passing kernel, 8094 us): 12 warps, RPW=9 (guarded to 100 rows),
// scalar FMA + reduce8/wsum, single-warp tail, 16 arrives/step.
__global__ void __launch_bounds__(THREADS, 1) lstm_main_kernel(
    const float* __restrict__ Whh0,
    const float* __restrict__ Wih1,
    const float* __restrict__ Whh1,
    const float* __restrict__ bih1,
    const float* __restrict__ bhh1)
{
    const int tid  = threadIdx.x;
    const int warp = tid >> 5;
    const int lane = tid & 31;
    const int role = blockIdx.x >> 4;    // 0=L0, 1=L1, 2=helpers
    const int rank = blockIdx.x & 15;

    if (role == 2) {
        // ---------------- helpers: u[t] = Wih1 * h0[t] + (bih1+bhh1) ----------------
        __shared__ __align__(16) float hb2[2][HIDP];   // staged h0 (double buffer)
        float w[RPW][13];
#pragma unroll
        for (int r = 0; r < RPW; r++) {
            int f = warp * RPW + r;
            bool fv = (f < ROWS);
            int row = fv ? ((f & 3) * 400 + rank * CELLS + (f >> 2)) : 0;
#pragma unroll
            for (int c = 0; c < 13; c++) {
                int k = lane + 32 * c;
                w[r][c] = (fv && k < HID) ? Wih1[(size_t)row * HID + k] : 0.f;
            }
        }
        float bias = 0.f;
        int doff = 0;
        bool stv = false;
        if (lane < RPW) {
            int f = warp * RPW + lane;
            if (f < ROWS) {
                int cell = rank * CELLS + (f >> 2);
                bias = bih1[(f & 3) * 400 + cell] + bhh1[(f & 3) * 400 + cell];
                doff = (f & 3) * 400 + cell;
                stv = true;
            }
        }
        for (int i = tid; i < 2 * HIDP; i += THREADS) ((float*)hb2)[i] = 0.f;
        __syncthreads();
        // bootstrap: stage h0[0] (slot 1) into hb2[0]
        if (warp == 1) {
            const unsigned* cp = g_cnt0 + 32;          // cnt0[1]
            while (ld_acq(cp) < CL) {}
            for (int i = lane; i < HID; i += 32)
                hb2[0][i] = __ldcg(g_h0 + (size_t)HID + i);
        }
        __syncthreads();

        for (int t = 0; t < T; t++) {
            // warps 1,2: poll + issue h0[t+1] loads EARLY (load-use distance = FMA phase)
            float pre[7];
            const bool pf = (warp == 1 || warp == 2) && (t < T - 1);
            if (pf) {
                const unsigned* cp = g_cnt0 + (size_t)(t + 2) * 32;
                while (ld_acq(cp) < CL) {}
                const float* hn = g_h0 + (size_t)(t + 2) * HID;
#pragma unroll
                for (int c = 0; c < 7; c++) {
                    int k = lane + 32 * ((warp - 1) + 2 * c);
                    pre[c] = (k < HID) ? __ldcg(hn + k) : 0.f;
                }
            }
            const float* hb = &hb2[t & 1][0];
            float hv[13];
#pragma unroll
            for (int c = 0; c < 13; c++) hv[c] = hb[lane + 32 * c];   // pads zero
            float a[RPW];
#pragma unroll
            for (int r = 0; r < RPW; r++) a[r] = 0.f;
#pragma unroll
            for (int c = 0; c < 13; c++)
#pragma unroll
                for (int r = 0; r < RPW; r++) a[r] = fmaf(w[r][c], hv[c], a[r]);
            float v  = reduce8(a, lane);          // lanes 0-7 -> sums of a[0..7]
            float v8 = wsum(a[8]);                // all lanes -> sum of a[8]
            if (stv) {
                float val = (lane < 8) ? v : v8;
                __stcg(g_u + (size_t)t * G4 + doff, val + bias);
            }
            if (pf) {
                float* dst = &hb2[(t + 1) & 1][0];
#pragma unroll
                for (int c = 0; c < 7; c++) {
                    int k = lane + 32 * ((warp - 1) + 2 * c);
                    if (k < HID) dst[k] = pre[c];
                }
            }
            __syncthreads();
            if (tid == 0) red_rel(g_cntu + (size_t)t * 32);
        }
        return;
    }

    // ---------------- recurrence clusters (L0 / L1) ----------------
    __shared__ __align__(16) float hbuf[2][HIDP];
    __shared__ __align__(16) float gsum[ROWS];
    __shared__ __align__(16) float hstage[28];
    __shared__ __align__(16) float4 ubuf4[2][CELLS];   // staged u (L1 only)
    __shared__ __align__(8)  unsigned long long mbar;

    const float* Whh = (role == 0) ? Whh0 : Whh1;
    float* ghout     = (role == 0) ? g_h0 : g_h1;

    float w[RPW][13];
#pragma unroll
    for (int r = 0; r < RPW; r++) {
        int f = warp * RPW + r;
        bool fv = (f < ROWS);
        int row = fv ? ((f & 3) * 400 + rank * CELLS + (f >> 2)) : 0;
#pragma unroll
        for (int c = 0; c < 13; c++) {
            int k = lane + 32 * c;
            w[r][c] = (fv && k < HID) ? Whh[(size_t)row * HID + k] : 0.f;
        }
    }
    const uint32_t hbuf_a = smem_u32(&hbuf[0][0]);
    const uint32_t mbar_a = smem_u32(&mbar);

    for (int i = tid; i < 2 * HIDP; i += THREADS) ((float*)hbuf)[i] = 0.f;
    if (tid == 0) mbar_init(mbar_a, CL);
    __syncthreads();
    // bootstrap: L1 stages u[0] (helpers produce it without L1 involvement — no cycle)
    if (role == 1 && warp == 1) {
        const unsigned* cu = g_cntu;                   // cntu[0]
        while (ld_acq(cu) < CL) {}
        if (lane < CELLS) {
            const float* up = g_u + rank * CELLS + lane;
            ubuf4[0][lane] = make_float4(__ldcg(up), __ldcg(up + 400),
                                         __ldcg(up + 800), __ldcg(up + 1200));
        }
    }
    asm volatile("barrier.cluster.arrive.aligned;" ::: "memory");
    asm volatile("barrier.cluster.wait.aligned;" ::: "memory");

    float cst = 0.f;
    for (int t = 0; t < T; t++) {
        float x0 = 0.f, x1 = 0.f, x2 = 0.f, x3 = 0.f;
        float4 upre = make_float4(0.f, 0.f, 0.f, 0.f);
        if (role == 0 && warp == 0 && lane < CELLS) {
            // xg0 precomputed: prefetch before wait (off critical path)
            const float* xg = g_xg0 + (size_t)t * G4 + rank * CELLS + lane;
            x0 = __ldg(xg); x1 = __ldg(xg + 400); x2 = __ldg(xg + 800); x3 = __ldg(xg + 1200);
        }
        if (role == 1 && warp == 1 && t < T - 1) {
            // prefetch u[t+1]: helpers run ahead -> poll hits; LDG latency hides under FMA
            const unsigned* cu = g_cntu + (size_t)(t + 1) * 32;
            while (ld_acq(cu) < CL) {}
            if (lane < CELLS) {
                const float* up = g_u + (size_t)(t + 1) * G4 + rank * CELLS + lane;
                upre = make_float4(__ldcg(up), __ldcg(up + 400),
                                   __ldcg(up + 800), __ldcg(up + 1200));
            }
        }
        // wait for h[t] (phase t-1); step 0 reads the zero-initialized buffer
        if (t > 0) mbar_wait_cluster(mbar_a, (unsigned)((t - 1) & 1));

        const float* hb = &hbuf[t & 1][0];
        float hv[13];
#pragma unroll
        for (int c = 0; c < 13; c++) hv[c] = hb[lane + 32 * c];   // pads are zero
        float a[RPW];
#pragma unroll
        for (int r = 0; r < RPW; r++) a[r] = 0.f;
#pragma unroll
        for (int c = 0; c < 13; c++)
#pragma unroll
            for (int r = 0; r < RPW; r++) a[r] = fmaf(w[r][c], hv[c], a[r]);
        float v  = reduce8(a, lane);
        float v8 = wsum(a[8]);
        {
            int f = warp * RPW + lane;
            if (lane < RPW && f < ROWS) gsum[f] = (lane < 8) ? v : v8;
        }
        if (role == 1 && warp == 1 && t < T - 1 && lane < CELLS)
            ubuf4[(t + 1) & 1][lane] = upre;
        __syncthreads();

        if (warp == 0) {
            if (lane < CELLS) {
                float4 gv = ((const float4*)gsum)[lane];   // [i,f,g,o] for this cell
                if (role == 1) {
                    float4 uv = ubuf4[t & 1][lane];         // staged u[t]
                    x0 = uv.x; x1 = uv.y; x2 = uv.z; x3 = uv.w;
                }
                float gi = sigf(gv.x + x0);
                float gf = sigf(gv.y + x1);
                float gg = tanhf_(gv.z + x2);
                float go = sigf(gv.w + x3);
                cst = gf * cst + gi * gg;
                float h = go * tanhf_(cst);
                hstage[lane] = h;
                __stcg(ghout + (size_t)(t + 1) * HID + rank * CELLS + lane, h);
            }
            __syncwarp();
            if (lane < CL) {
                // copy this CTA's 25-float slice into peer `lane`'s next h buffer
                float s[CELLS];
#pragma unroll
                for (int q = 0; q < CELLS; q++) s[q] = hstage[q];
                uint32_t dst = mapa_u32(
                    hbuf_a + (uint32_t)(((t + 1) & 1) * HIDP + rank * CELLS) * 4u,
                    (uint32_t)lane);
#pragma unroll
                for (int q = 0; q < CELLS; q++) st_cluster_b32(dst + 4u * q, s[q]);
                mbar_arrive_remote(mbar_a, (uint32_t)lane);
            }
            __syncwarp();
            if (role == 0 && lane == 0) red_rel(g_cnt0 + (size_t)(t + 1) * 32);
        }
    }
    // final cluster barrier: no CTA exits while peers may still write its smem
    asm volatile("barrier.cluster.arrive.aligned;" ::: "memory");
    asm volatile("barrier.cluster.wait.aligned;" ::: "memory");
}

// ---------------- kernel C: rtoken = rnn_out @ fcW^T + fcb ----------------
// R17 change: BT 64 -> 32 (grid 64 -> 128 CTAs) to lift occupancy of this
// grid-starved GEMM (ncu: occ=12.5%, 86us). Per-thread tile 4x5.
__global__ void __launch_bounds__(256, 1) rtoken_kernel(
    const float* __restrict__ fcW, const float* __restrict__ fcb, float* __restrict__ out)
{
    __shared__ float xs[32][53];
    __shared__ float ws[160][53];
    const int bt0 = blockIdx.x * 32;
    const int tid = threadIdx.x;
    float acc[4][5];
#pragma unroll
    for (int i = 0; i < 4; i++)
#pragma unroll
        for (int r = 0; r < 5; r++) acc[i][r] = 0.f;

    for (int ch = 0; ch < 8; ch++) {
        int k0 = ch * 50;
        for (int i = tid; i < 32 * 50; i += 256) {
            int tt = i / 50, kk = i - tt * 50;
            xs[tt][kk] = g_h1[(size_t)(bt0 + tt + 1) * HID + k0 + kk];
        }
        for (int i = tid; i < 160 * 50; i += 256) {
            int rr = i / 50, kk = i - rr * 50;
            ws[rr][kk] = (rr < E3) ? fcW[rr * HID + k0 + kk] : 0.f;
        }
        __syncthreads();
        const int tr = tid & 31, tc = tid >> 5;
#pragma unroll 5
        for (int kk = 0; kk < 50; kk++) {
            float a[4], wv[5];
#pragma unroll
            for (int i = 0; i < 4; i++) a[i] = xs[tc * 4 + i][kk];
#pragma unroll
            for (int r = 0; r < 5; r++) wv[r] = ws[tr * 5 + r][kk];
#pragma unroll
            for (int i = 0; i < 4; i++)
#pragma unroll
                for (int r = 0; r < 5; r++) acc[i][r] = fmaf(a[i], wv[r], acc[i][r]);
        }
        __syncthreads();
    }
    const int tr = tid & 31, tc = tid >> 5;
#pragma unroll
    for (int r = 0; r < 5; r++) {
        int rg = tr * 5 + r;
        if (rg < E3) {
            float bias = fcb[rg];
#pragma unroll
            for (int i = 0; i < 4; i++) {
                int t = bt0 + tc * 4 + i;
                out[(size_t)t * E3 + rg] = acc[i][r] + bias;
            }
        }
    }
}

// ---------------- kernel D: context fill ----------------
__global__ void __launch_bounds__(128, 1) ctx_kernel(
    const float* __restrict__ actW, const float* __restrict__ actb,
    const float* __restrict__ Dp, float* __restrict__ out)
{
    const int t = blockIdx.x;
    const int warp = threadIdx.x >> 5, lane = threadIdx.x & 31;
    __shared__ float red[4];
    const float* hr = g_h1 + (size_t)(t + 1) * HID;
    const float* wrow = (warp < 3) ? (actW + warp * HID) : Dp;
    float acc = 0.f;
#pragma unroll
    for (int c = 0; c < 13; c++) {
        int k = lane + 32 * c;
        if (k < HID) acc = fmaf(__ldg(wrow + k), __ldg(hr + k), acc);
    }
    acc = wsum(acc);
    if (lane == 0) red[warp] = acc + ((warp < 3) ? actb[warp] : 0.f);
    __syncthreads();
    float l0 = red[0], l1 = red[1], l2 = red[2], d = red[3];
    float m = fmaxf(l0, fmaxf(l1, l2));
    float e0 = __expf(l0 - m), e1 = __expf(l1 - m), e2 = __expf(l2 - m);
    float p0 = __fdividef(e0, e0 + e1 + e2);
    float v = p0 * sigf(d);

    float4* dst = (float4*)(out + OFF_CTX + (size_t)t * 32 * HID);
    float4 vz = make_float4(v, v, v, v);
    float4 z = make_float4(0.f, 0.f, 0.f, 0.f);
    for (int q = threadIdx.x; q < 3200; q += 128) {
        __stcs(dst + q, (q < 100) ? vz : z);
    }
}

// ---------------- kernel E1: key lstm gates ----------------
__global__ void __launch_bounds__(128, 1) keygate_kernel(
    const float* __restrict__ kWih, const float* __restrict__ kbih, const float* __restrict__ kbhh)
{
    const int gw = blockIdx.x * 4 + (threadIdx.x >> 5);
    const int lane = threadIdx.x & 31;
    const float* hr = g_h1 + (size_t)T * HID;
    float hv[13];
#pragma unroll
    for (int c = 0; c < 13; c++) {
        int k = lane + 32 * c;
        hv[c] = (k < HID) ? __ldg(hr + k) : 0.f;
    }
    for (int rr = 0; rr < 30; rr++) {
        int r = gw * 30 + rr;
        float acc = 0.f;
#pragma unroll
        for (int c = 0; c < 13; c++) {
            int k = lane + 32 * c;
            if (k < HID) acc = fmaf(__ldg(kWih + (size_t)r * HID + k), hv[c], acc);
        }
        acc = wsum(acc);
        if (lane == 0) g_kgate[r] = acc + kbih[r] + kbhh[r];
    }
}

// ---------------- kernel E2: kh nonlinearity + ktoken ----------------
__global__ void __launch_bounds__(512, 1) keyout_kernel(
    const float* __restrict__ kfcW, const float* __restrict__ kfcb, float* __restrict__ out)
{
    __shared__ float kh[KEY];
    const int tid = threadIdx.x;
    if (tid < KEY) {
        float gi = g_kgate[tid], gg = g_kgate[600 + tid], go = g_kgate[900 + tid];
        float c = sigf(gi) * tanhf_(gg);
        kh[tid] = sigf(go) * tanhf_(c);
    }
    __syncthreads();
    const int warp = tid >> 5, lane = tid & 31;
    for (int rr = 0; rr < 25; rr++) {
        int r = warp * 25 + rr;
        float acc = 0.f;
#pragma unroll
        for (int c = 0; c < 10; c++) {
            int k = lane + 32 * c;
            if (k < KEY) acc = fmaf(__ldg(kfcW + (size_t)r * KEY + k), kh[k], acc);
        }
        acc = wsum(acc);
        if (lane == 0) out[OFF_KTOK + r] = acc + kfcb[r];
    }
}

// ---------------- launch ----------------
extern "C" void kernel_launch(void* const* d_in, const int* in_sizes, int n_in,
                              void* d_out, int out_size)
{
    const int*   xr       = (const int*)d_in[0];
    const int*   xcpc     = (const int*)d_in[1];
    const int*   xma      = (const int*)d_in[2];
    const float* em       = (const float*)d_in[3];
    const float* ec       = (const float*)d_in[4];
    const float* er       = (const float*)d_in[5];
    const float* Wih0     = (const float*)d_in[6];
    const float* Whh0     = (const float*)d_in[7];
    const float* bih0     = (const float*)d_in[8];
    const float* bhh0     = (const float*)d_in[9];
    const float* Wih1     = (const float*)d_in[10];
    const float* Whh1     = (const float*)d_in[11];
    const float* bih1     = (const float*)d_in[12];
    const float* bhh1     = (const float*)d_in[13];
    const float* fcW      = (const float*)d_in[14];
    const float* fcb      = (const float*)d_in[15];
    const float* actW     = (const float*)d_in[16];
    const float* actb     = (const float*)d_in[17];
    const float* Dp       = (const float*)d_in[18];
    const float* kWih     = (const float*)d_in[19];
    const float* kbih     = (const float*)d_in[21];
    const float* kbhh     = (const float*)d_in[22];
    const float* kfcW     = (const float*)d_in[23];
    const float* kfcb     = (const float*)d_in[24];
    float* out = (float*)d_out;

    init_kernel<<<((T + 1) * 32 + 255) / 256, 256>>>();
    xg0_kernel<<<dim3(T / 64, G4 / 160), 256>>>(xr, xcpc, xma, em, ec, er, Wih0, bih0, bhh0);
    noop_kernel<<<1, 32>>>();   // spacer: keeps lstm in the ncu capture slot

    // 16-CTA clusters (non-portable size): 3 clusters = L0 / L1 / helpers
    cudaFuncSetAttribute(lstm_main_kernel,
                         cudaFuncAttributeNonPortableClusterSizeAllowed, 1);
    cudaLaunchConfig_t cfg = {};
    cfg.gridDim = {48, 1, 1};
    cfg.blockDim = {THREADS, 1, 1};
    cfg.dynamicSmemBytes = 0;
    cfg.stream = 0;
    cudaLaunchAttribute attrs[1];
    attrs[0].id = cudaLaunchAttributeClusterDimension;
    attrs[0].val.clusterDim = {CL, 1, 1};
    cfg.attrs = attrs;
    cfg.numAttrs = 1;
    cudaLaunchKernelEx(&cfg, lstm_main_kernel, Whh0, Wih1, Whh1, bih1, bhh1);

    rtoken_kernel<<<T / 32, 256>>>(fcW, fcb, out);
    ctx_kernel<<<T, 128>>>(actW, actb, Dp, out);
    keygate_kernel<<<10, 128>>>(kWih, kbih, kbhh);
    keyout_kernel<<<1, 512>>>(kfcW, kfcb, out);
}